// round 2
// baseline (speedup 1.0000x reference)
#include <cuda_runtime.h>

// GCN_8057358647356 — fp32 baseline with algebraic reduction.
// B=64 graphs, N=1024 nodes, F=128, H=256.
//
// Pipeline:
//   T  = adj @ X                      (batched, M=1024 N=128 K=1024)  -> S1
//   S  = relu(T @ W0 + b0)            (flat,    M=65536 N=256 K=128)  -> S2
//   U  = S @ W1                       (flat,    M=65536 N=256 K=256)  -> S1
//   V  = relu(adj @ U + b1)           (batched, M=1024 N=256 K=1024)  -> S2
//   z  = adj[:,0,:] @ V               (per-graph vector·matrix)       -> g_z
//   out= relu(z @ W2 + b2) @ Wl + bl  (tiny per-graph head)

#define BATCH 64
#define NNODE 1024
#define FEAT  128
#define HID   256

__device__ float g_S1[BATCH * NNODE * HID];   // 64 MB scratch (ping)
__device__ float g_S2[BATCH * NNODE * HID];   // 64 MB scratch (pong)
__device__ float g_z[BATCH * HID];

// ---------------------------------------------------------------------------
// 128x128 tile SGEMM, K-step 8, 256 threads, 8x8 accum per thread (4x4 quads).
// Optional fused bias + relu epilogue. Batched via blockIdx.z with strides.
// Requires: M,N multiples of 128; K multiple of 8; 16B-aligned rows (true here).
// ---------------------------------------------------------------------------
template <bool BIAS_RELU>
__global__ __launch_bounds__(256) void sgemm128(
    const float* __restrict__ A, const float* __restrict__ B,
    float* __restrict__ C, const float* __restrict__ bias,
    int M, int N, int K,
    long long sA, long long sB, long long sC)
{
    A += (long long)blockIdx.z * sA;
    B += (long long)blockIdx.z * sB;
    C += (long long)blockIdx.z * sC;

    __shared__ float As[8][128];
    __shared__ float Bs[8][128];

    const int tid = threadIdx.x;
    const int m0 = blockIdx.y * 128;
    const int n0 = blockIdx.x * 128;

    // A-tile load: 128 rows x 8 cols; each thread one float4 along K.
    const int arow = tid >> 1;
    const int acol = (tid & 1) * 4;
    // B-tile load: 8 rows x 128 cols; each thread one float4 along N.
    const int brow = tid >> 5;
    const int bcol = (tid & 31) * 4;

    const float* Ap = A + (long long)(m0 + arow) * K + acol;
    const float* Bp = B + (long long)brow * N + (n0 + bcol);

    const int tx = tid & 15;
    const int ty = tid >> 4;

    float acc[8][8];
#pragma unroll
    for (int i = 0; i < 8; i++)
#pragma unroll
        for (int j = 0; j < 8; j++) acc[i][j] = 0.f;

    for (int k = 0; k < K; k += 8) {
        float4 av = *(const float4*)(Ap + k);
        float4 bv = *(const float4*)(Bp + (long long)k * N);
        As[acol + 0][arow] = av.x;
        As[acol + 1][arow] = av.y;
        As[acol + 2][arow] = av.z;
        As[acol + 3][arow] = av.w;
        *(float4*)&Bs[brow][bcol] = bv;
        __syncthreads();

#pragma unroll
        for (int kk = 0; kk < 8; kk++) {
            float a[8], b[8];
            *(float4*)(a)     = *(const float4*)&As[kk][ty * 4];
            *(float4*)(a + 4) = *(const float4*)&As[kk][64 + ty * 4];
            *(float4*)(b)     = *(const float4*)&Bs[kk][tx * 4];
            *(float4*)(b + 4) = *(const float4*)&Bs[kk][64 + tx * 4];
#pragma unroll
            for (int i = 0; i < 8; i++)
#pragma unroll
                for (int j = 0; j < 8; j++)
                    acc[i][j] = fmaf(a[i], b[j], acc[i][j]);
        }
        __syncthreads();
    }

    // Epilogue: rows in two 64-row halves, cols in two 64-col halves.
#pragma unroll
    for (int i = 0; i < 8; i++) {
        const int r = m0 + ((i < 4) ? (ty * 4 + i) : (64 + ty * 4 + (i - 4)));
        float* Crow = C + (long long)r * N + n0;
#pragma unroll
        for (int half = 0; half < 2; half++) {
            const int cbase = half * 64 + tx * 4;
            float4 v;
            v.x = acc[i][half * 4 + 0];
            v.y = acc[i][half * 4 + 1];
            v.z = acc[i][half * 4 + 2];
            v.w = acc[i][half * 4 + 3];
            if (BIAS_RELU) {
                const float* bp = bias + n0 + cbase;
                v.x = fmaxf(v.x + bp[0], 0.f);
                v.y = fmaxf(v.y + bp[1], 0.f);
                v.z = fmaxf(v.z + bp[2], 0.f);
                v.w = fmaxf(v.w + bp[3], 0.f);
            }
            *(float4*)(Crow + cbase) = v;
        }
    }
}

// ---------------------------------------------------------------------------
// z[b,h] = sum_n adj[b,0,n] * V[b,n,h]   (adj row 0 dot against node dim)
// ---------------------------------------------------------------------------
__global__ __launch_bounds__(256) void rowdot_kernel(
    const float* __restrict__ adj, const float* __restrict__ V,
    float* __restrict__ z)
{
    const int b = blockIdx.x;
    const int h = threadIdx.x;   // 0..255
    __shared__ float ar[NNODE];
    for (int i = h; i < NNODE; i += 256)
        ar[i] = adj[(long long)b * NNODE * NNODE + i];
    __syncthreads();

    const float* vp = V + (long long)b * NNODE * HID + h;
    float a0 = 0.f, a1 = 0.f, a2 = 0.f, a3 = 0.f;
#pragma unroll 4
    for (int n = 0; n < NNODE; n += 4) {
        a0 = fmaf(ar[n + 0], vp[(long long)(n + 0) * HID], a0);
        a1 = fmaf(ar[n + 1], vp[(long long)(n + 1) * HID], a1);
        a2 = fmaf(ar[n + 2], vp[(long long)(n + 2) * HID], a2);
        a3 = fmaf(ar[n + 3], vp[(long long)(n + 3) * HID], a3);
    }
    z[b * HID + h] = (a0 + a1) + (a2 + a3);
}

// ---------------------------------------------------------------------------
// out[b,f] = (relu(z[b] @ W2 + b2)) @ Wl + bl
// ---------------------------------------------------------------------------
__global__ __launch_bounds__(256) void head_kernel(
    const float* __restrict__ z,
    const float* __restrict__ W2, const float* __restrict__ b2,
    const float* __restrict__ Wl, const float* __restrict__ bl,
    float* __restrict__ out)
{
    const int b = blockIdx.x;
    const int t = threadIdx.x;   // 0..255
    __shared__ float zs[HID], ts[HID];
    zs[t] = z[b * HID + t];
    __syncthreads();

    float acc = b2[t];
#pragma unroll 8
    for (int h = 0; h < HID; h++)
        acc = fmaf(zs[h], W2[h * HID + t], acc);
    ts[t] = fmaxf(acc, 0.f);
    __syncthreads();

    if (t < FEAT) {
        float o = bl[t];
#pragma unroll 8
        for (int h = 0; h < HID; h++)
            o = fmaf(ts[h], Wl[h * FEAT + t], o);
        out[b * FEAT + t] = o;
    }
}

// ---------------------------------------------------------------------------
extern "C" void kernel_launch(void* const* d_in, const int* in_sizes, int n_in,
                              void* d_out, int out_size)
{
    const float* embs = (const float*)d_in[0];  // [64,1024,128]
    const float* adj  = (const float*)d_in[1];  // [64,1024,1024]
    const float* W0   = (const float*)d_in[2];  // [128,256]
    const float* b0   = (const float*)d_in[3];  // [256]
    const float* W1   = (const float*)d_in[4];  // [256,256]
    const float* b1   = (const float*)d_in[5];  // [256]
    const float* W2   = (const float*)d_in[6];  // [256,256]
    const float* b2   = (const float*)d_in[7];  // [256]
    const float* Wl   = (const float*)d_in[8];  // [256,128]
    const float* bl   = (const float*)d_in[9];  // [128]
    float* out = (float*)d_out;                 // [64,128]

    float *S1, *S2, *z;
    cudaGetSymbolAddress((void**)&S1, g_S1);
    cudaGetSymbolAddress((void**)&S2, g_S2);
    cudaGetSymbolAddress((void**)&z,  g_z);

    dim3 blk(256);

    // 1) T = adj @ X : batched [1024 x 128], K=1024
    sgemm128<false><<<dim3(1, 8, 64), blk>>>(
        adj, embs, S1, nullptr,
        NNODE, FEAT, NNODE,
        (long long)NNODE * NNODE, (long long)NNODE * FEAT, (long long)NNODE * FEAT);

    // 2) S = relu(T @ W0 + b0) : flat [65536 x 256], K=128
    sgemm128<true><<<dim3(2, 512, 1), blk>>>(
        S1, W0, S2, b0,
        BATCH * NNODE, HID, FEAT, 0, 0, 0);

    // 3) U = S @ W1 : flat [65536 x 256], K=256
    sgemm128<false><<<dim3(2, 512, 1), blk>>>(
        S2, W1, S1, nullptr,
        BATCH * NNODE, HID, HID, 0, 0, 0);

    // 4) V = relu(adj @ U + b1) : batched [1024 x 256], K=1024
    sgemm128<true><<<dim3(2, 8, 64), blk>>>(
        adj, S1, S2, b1,
        NNODE, HID, NNODE,
        (long long)NNODE * NNODE, (long long)NNODE * HID, (long long)NNODE * HID);

    // 5) z = adj[:,0,:] @ V
    rowdot_kernel<<<64, 256>>>(adj, S2, z);

    // 6) out = relu(z @ W2 + b2) @ Wl + bl
    head_kernel<<<64, 256>>>(z, W2, b2, Wl, bl, out);
}

// round 5
// speedup vs baseline: 2.6351x; 2.6351x over previous
#include <cuda_runtime.h>
#include <cstdint>

#define BATCH 64
#define NNODE 1024
#define FEAT  128
#define HID   256

// scratch (device globals; allocation-free rule)
__device__ float g_S1[BATCH * NNODE * HID];     // T  [B,1024,128] (ldc=128)
__device__ float g_S2[BATCH * NNODE * HID];     // S, later V
__device__ float g_S3[BATCH * NNODE * HID];     // U
__device__ float g_XR[BATCH * NNODE * FEAT];    // rna(embs)
__device__ float g_W0R[FEAT * HID];
__device__ float g_W1R[HID * HID];
__device__ float g_z[BATCH * HID];

__device__ __forceinline__ float rna(float x) {
    float r; asm("cvt.rna.tf32.f32 %0, %1;" : "=f"(r) : "f"(x)); return r;
}
__device__ __forceinline__ unsigned su32(const void* p) {
    unsigned a;
    asm("{ .reg .u64 t; cvta.to.shared.u64 t, %1; cvt.u32.u64 %0, t; }" : "=r"(a) : "l"(p));
    return a;
}
__device__ __forceinline__ void cp16(unsigned s, const float* g) {
    asm volatile("cp.async.cg.shared.global [%0], [%1], 16;" :: "r"(s), "l"(g) : "memory");
}

__global__ void round4_kernel(const float4* __restrict__ s, float4* __restrict__ d, int n4) {
    int i = blockIdx.x * blockDim.x + threadIdx.x;
    if (i < n4) {
        float4 v = s[i];
        v.x = rna(v.x); v.y = rna(v.y); v.z = rna(v.z); v.w = rna(v.w);
        d[i] = v;
    }
}

// ---------------------------------------------------------------------------
// tf32 mma.sync GEMM: C[m,n] = sum_k A[m,k] * B[k,n]
//   A [M,K] row-major fp32 (cvt.rna applied on smem-store path)
//   B [K,N] row-major, pre-rounded to tf32
// CTA tile 128x128, K-chunk 32, 256 threads (8 warps, 2x4), double-buffered.
// flags: 1 = +bias,relu ; 2 = round output to tf32
// grid: (Mtiles, Ntiles, batch)
// ---------------------------------------------------------------------------
#define AS_PITCH 36
#define BS_PITCH 132
#define AS_BUF (128 * AS_PITCH)            // floats per A buffer
#define BS_BUF (32 * BS_PITCH)             // floats per B buffer
#define GSMEM ((2 * AS_BUF + 2 * BS_BUF) * 4)

__global__ __launch_bounds__(256, 2) void gemm_mma(
    const float* __restrict__ A, const float* __restrict__ B,
    float* __restrict__ C, const float* __restrict__ bias,
    int K, int nc, int ldb, int ldc,
    long long sA, long long sB, long long sC, int flags)
{
    extern __shared__ float sm[];
    float* Asm = sm;                       // [2][128][AS_PITCH]
    float* Bsm = sm + 2 * AS_BUF;          // [2][32][BS_PITCH]

    const int tid = threadIdx.x, wid = tid >> 5, lane = tid & 31;
    const int g = lane >> 2, tig = lane & 3;
    const int wm = (wid & 1) * 64, wn = (wid >> 1) * 32;
    const int m0 = blockIdx.x * 128, n0 = blockIdx.y * 128;

    A += (long long)blockIdx.z * sA;
    B += (long long)blockIdx.z * sB;
    C += (long long)blockIdx.z * sC;

    // load indices: A tile 128x32 (8 float4/row), B tile 32x128 (32 float4/row)
    const int ar = tid >> 1 << 0;          // not used; per-i below
    (void)ar;

    float4 areg[4];
    // ---- prologue: ldg A chunk 0, cp.async B chunk 0 -> buf 0
#pragma unroll
    for (int i = 0; i < 4; ++i) {
        const int f = tid + i * 256, row = f >> 3, seg = f & 7;
        areg[i] = *(const float4*)(A + (long long)(m0 + row) * K + seg * 4);
    }
#pragma unroll
    for (int i = 0; i < 4; ++i) {
        const int f = tid + i * 256, row = f >> 5, c4 = f & 31;
        cp16(su32(Bsm + row * BS_PITCH + c4 * 4),
             B + (long long)row * ldb + n0 + c4 * 4);
    }
    asm volatile("cp.async.commit_group;" ::: "memory");

    float cacc[4][4][4];
#pragma unroll
    for (int mt = 0; mt < 4; ++mt)
#pragma unroll
        for (int nt = 0; nt < 4; ++nt)
#pragma unroll
            for (int r = 0; r < 4; ++r) cacc[mt][nt][r] = 0.f;

    for (int c = 0; c < nc; ++c) {
        const int buf = c & 1;
        // stage A regs -> smem (with rna)
#pragma unroll
        for (int i = 0; i < 4; ++i) {
            const int f = tid + i * 256, row = f >> 3, seg = f & 7;
            float4 v = areg[i];
            v.x = rna(v.x); v.y = rna(v.y); v.z = rna(v.z); v.w = rna(v.w);
            *(float4*)(Asm + buf * AS_BUF + row * AS_PITCH + seg * 4) = v;
        }
        if (c + 1 < nc) {
            const float* An = A + (c + 1) * 32;
            const float* Bn = B + (long long)(c + 1) * 32 * ldb;
#pragma unroll
            for (int i = 0; i < 4; ++i) {
                const int f = tid + i * 256, row = f >> 3, seg = f & 7;
                areg[i] = *(const float4*)(An + (long long)(m0 + row) * K + seg * 4);
            }
#pragma unroll
            for (int i = 0; i < 4; ++i) {
                const int f = tid + i * 256, row = f >> 5, c4 = f & 31;
                cp16(su32(Bsm + (buf ^ 1) * BS_BUF + row * BS_PITCH + c4 * 4),
                     Bn + (long long)row * ldb + n0 + c4 * 4);
            }
            asm volatile("cp.async.commit_group;" ::: "memory");
            asm volatile("cp.async.wait_group 1;" ::: "memory");
        } else {
            asm volatile("cp.async.wait_group 0;" ::: "memory");
        }
        __syncthreads();

        const float* as = Asm + buf * AS_BUF + wm * AS_PITCH;
        const float* bs = Bsm + buf * BS_BUF + wn;
#pragma unroll
        for (int ks = 0; ks < 4; ++ks) {
            const int kk = ks * 8;
            unsigned a[4][4], b[4][2];
#pragma unroll
            for (int mt = 0; mt < 4; ++mt) {
                const float* ap = as + (mt * 16 + g) * AS_PITCH + kk + tig;
                a[mt][0] = __float_as_uint(ap[0]);
                a[mt][1] = __float_as_uint(ap[8 * AS_PITCH]);
                a[mt][2] = __float_as_uint(ap[4]);
                a[mt][3] = __float_as_uint(ap[8 * AS_PITCH + 4]);
            }
#pragma unroll
            for (int nt = 0; nt < 4; ++nt) {
                const float* bp = bs + (kk + tig) * BS_PITCH + nt * 8 + g;
                b[nt][0] = __float_as_uint(bp[0]);
                b[nt][1] = __float_as_uint(bp[4 * BS_PITCH]);
            }
#pragma unroll
            for (int mt = 0; mt < 4; ++mt)
#pragma unroll
                for (int nt = 0; nt < 4; ++nt)
                    asm volatile(
                        "mma.sync.aligned.m16n8k8.row.col.f32.tf32.tf32.f32 "
                        "{%0,%1,%2,%3}, {%4,%5,%6,%7}, {%8,%9}, {%0,%1,%2,%3};"
                        : "+f"(cacc[mt][nt][0]), "+f"(cacc[mt][nt][1]),
                          "+f"(cacc[mt][nt][2]), "+f"(cacc[mt][nt][3])
                        : "r"(a[mt][0]), "r"(a[mt][1]), "r"(a[mt][2]), "r"(a[mt][3]),
                          "r"(b[nt][0]), "r"(b[nt][1]));
        }
        __syncthreads();
    }

    // ---- epilogue
#pragma unroll
    for (int mt = 0; mt < 4; ++mt) {
#pragma unroll
        for (int h = 0; h < 2; ++h) {
            const int r = m0 + wm + mt * 16 + g + h * 8;
            float* Crow = C + (long long)r * ldc;
#pragma unroll
            for (int nt = 0; nt < 4; ++nt) {
                const int col = n0 + wn + nt * 8 + 2 * tig;
                float x0 = cacc[mt][nt][h * 2 + 0];
                float x1 = cacc[mt][nt][h * 2 + 1];
                if (flags & 1) {
                    x0 = fmaxf(x0 + bias[col], 0.f);
                    x1 = fmaxf(x1 + bias[col + 1], 0.f);
                }
                if (flags & 2) { x0 = rna(x0); x1 = rna(x1); }
                float2 v; v.x = x0; v.y = x1;
                *(float2*)(Crow + col) = v;
            }
        }
    }
}

// --------------------------- exact fp32 tail -------------------------------
__global__ __launch_bounds__(256) void rowdot_kernel(
    const float* __restrict__ adj, const float* __restrict__ V, float* __restrict__ z)
{
    const int b = blockIdx.x, h = threadIdx.x;
    __shared__ float ar[NNODE];
    for (int i = h; i < NNODE; i += 256)
        ar[i] = adj[(long long)b * NNODE * NNODE + i];
    __syncthreads();
    const float* vp = V + (long long)b * NNODE * HID + h;
    float a0 = 0.f, a1 = 0.f, a2 = 0.f, a3 = 0.f;
#pragma unroll 4
    for (int n = 0; n < NNODE; n += 4) {
        a0 = fmaf(ar[n + 0], vp[(long long)(n + 0) * HID], a0);
        a1 = fmaf(ar[n + 1], vp[(long long)(n + 1) * HID], a1);
        a2 = fmaf(ar[n + 2], vp[(long long)(n + 2) * HID], a2);
        a3 = fmaf(ar[n + 3], vp[(long long)(n + 3) * HID], a3);
    }
    z[b * HID + h] = (a0 + a1) + (a2 + a3);
}

__global__ __launch_bounds__(256) void head_kernel(
    const float* __restrict__ z, const float* __restrict__ W2, const float* __restrict__ b2,
    const float* __restrict__ Wl, const float* __restrict__ bl, float* __restrict__ out)
{
    const int b = blockIdx.x, t = threadIdx.x;
    __shared__ float zs[HID], ts[HID];
    zs[t] = z[b * HID + t];
    __syncthreads();
    float acc = b2[t];
#pragma unroll 8
    for (int h = 0; h < HID; h++) acc = fmaf(zs[h], W2[h * HID + t], acc);
    ts[t] = fmaxf(acc, 0.f);
    __syncthreads();
    if (t < FEAT) {
        float o = bl[t];
#pragma unroll 8
        for (int h = 0; h < HID; h++) o = fmaf(ts[h], Wl[h * FEAT + t], o);
        out[b * FEAT + t] = o;
    }
}

// ---------------------------------------------------------------------------
extern "C" void kernel_launch(void* const* d_in, const int* in_sizes, int n_in,
                              void* d_out, int out_size)
{
    const float* embs = (const float*)d_in[0];
    const float* adj  = (const float*)d_in[1];
    const float* W0   = (const float*)d_in[2];
    const float* b0   = (const float*)d_in[3];
    const float* W1   = (const float*)d_in[4];
    const float* b1   = (const float*)d_in[5];
    const float* W2   = (const float*)d_in[6];
    const float* b2   = (const float*)d_in[7];
    const float* Wl   = (const float*)d_in[8];
    const float* bl   = (const float*)d_in[9];
    float* out = (float*)d_out;

    float *S1, *S2, *S3, *XR, *W0R, *W1R, *z;
    cudaGetSymbolAddress((void**)&S1, g_S1);
    cudaGetSymbolAddress((void**)&S2, g_S2);
    cudaGetSymbolAddress((void**)&S3, g_S3);
    cudaGetSymbolAddress((void**)&XR, g_XR);
    cudaGetSymbolAddress((void**)&W0R, g_W0R);
    cudaGetSymbolAddress((void**)&W1R, g_W1R);
    cudaGetSymbolAddress((void**)&z, g_z);

    cudaFuncSetAttribute(gemm_mma, cudaFuncAttributeMaxDynamicSharedMemorySize, GSMEM);

    const long long NN = (long long)NNODE * NNODE;
    const long long NH = (long long)NNODE * HID;
    const long long NF = (long long)NNODE * FEAT;
    dim3 t256(256);

    // prep: round B operands to tf32 (keep natural [K,N] layouts)
    round4_kernel<<<8192, 256>>>((const float4*)embs, (float4*)XR, BATCH * NNODE * FEAT / 4);
    round4_kernel<<<32, 256>>>((const float4*)W0, (float4*)W0R, FEAT * HID / 4);
    round4_kernel<<<64, 256>>>((const float4*)W1, (float4*)W1R, HID * HID / 4);

    // 1) T = adj @ X   [per-graph 1024x128, K=1024] -> S1 (rounded out)
    gemm_mma<<<dim3(8, 1, 64), t256, GSMEM>>>(adj, XR, S1, nullptr,
        NNODE, 32, FEAT, FEAT, NN, NF, NF, 2);
    // 2) S = relu(T @ W0 + b0)  [65536x256, K=128] -> S2 (relu+rounded)
    gemm_mma<<<dim3(512, 2, 1), t256, GSMEM>>>(S1, W0R, S2, b0,
        FEAT, 4, HID, HID, 0, 0, 0, 3);
    // 3) U = S @ W1   [65536x256, K=256] -> S3 (rounded)
    gemm_mma<<<dim3(512, 2, 1), t256, GSMEM>>>(S2, W1R, S3, nullptr,
        HID, 8, HID, HID, 0, 0, 0, 2);
    // 4) V = relu(adj @ U + b1) [per-graph 1024x256, K=1024] -> S2 (fp32)
    gemm_mma<<<dim3(8, 2, 64), t256, GSMEM>>>(adj, S3, S2, b1,
        NNODE, 32, HID, HID, NN, NH, NH, 1);

    // exact tail
    rowdot_kernel<<<64, 256>>>(adj, S2, z);
    head_kernel<<<64, 256>>>(z, W2, b2, Wl, bl, out);
}